// round 6
// baseline (speedup 1.0000x reference)
#include <cuda_runtime.h>

#define TPB 64
#define NSWEEP 6

// ---------------------------------------------------------------------------
// Compile-time index helpers (all call sites have constant args -> fold away).
// ---------------------------------------------------------------------------

// Lexicographic index of combination (a<b<c) out of C(7,3)=35.
__device__ __forceinline__ int tri_idx(int a, int b, int c) {
    int idx = 0;
#pragma unroll
    for (int x = 0; x < 7; ++x)
        if (x < a) idx += (6 - x) * (5 - x) / 2;
    idx += ((b - a - 1) * (12 - a - b)) / 2;
    idx += (c - b - 1);
    return idx;
}

// pf(a, m, n) with m<n, a distinct from both: phi index + sign.
__device__ __forceinline__ void pf_ref(int a, int m, int n, int &idx, double &sg) {
    if (a < m)      { idx = tri_idx(a, m, n); sg =  1.0; }
    else if (a < n) { idx = tri_idx(m, a, n); sg = -1.0; }
    else            { idx = tri_idx(m, n, a); sg =  1.0; }
}

// Sign of the permutation (k,l,m,n,p,q,r) of (0..6).
__device__ __forceinline__ double eps_sign7(int k, int l, int m, int n,
                                            int p, int q, int r) {
    int arr[7] = {k, l, m, n, p, q, r};
    int inv = 0;
#pragma unroll
    for (int x = 0; x < 7; ++x)
#pragma unroll
        for (int y = x + 1; y < 7; ++y)
            inv += (arr[x] > arr[y]) ? 1 : 0;
    return (inv & 1) ? -1.0 : 1.0;
}

// Upper-triangle packed index for 7x7 symmetric, requires i<=j.
__device__ __forceinline__ int ui(int i, int j) {
    return 7 * i - (i * (i - 1)) / 2 + (j - i);
}
__device__ __forceinline__ int uis(int i, int j) {   // symmetric access
    return (i <= j) ? ui(i, j) : ui(j, i);
}

// ---------------------------------------------------------------------------
// Kernel: one thread per batch element.
// ---------------------------------------------------------------------------
__global__ void __launch_bounds__(TPB)
positivity_kernel(const float* __restrict__ phi, float* __restrict__ out, int n)
{
    __shared__ float sphi[TPB * 35];

    const int base = blockIdx.x * TPB;
    {   // coalesced staging of this block's phi rows
        int limit = (n - base) * 35;
        if (limit > TPB * 35) limit = TPB * 35;
        for (int idx = threadIdx.x; idx < limit; idx += TPB)
            sphi[idx] = phi[(long long)base * 35 + idx];
    }
    __syncthreads();

    const int b = base + threadIdx.x;
    if (b >= n) return;

    // phi components, widened to double (exact).
    double P[35];
#pragma unroll
    for (int t = 0; t < 35; ++t) P[t] = (double)sphi[threadIdx.x * 35 + t];

    // -----------------------------------------------------------------
    // Bd[i<=j] (packed) = (1/6) * Sum_{k<l} pf(i,k,l) *
    //      Sum_{m<n in comp(k,l)} eps(k,l,m,n,p,q,r)*P[pqr]*pf(j,m,n)
    // Exact in fp64 (products of fp32-exact doubles are exact; the
    // cancellation-heavy additions carry 53 bits). This phase is the
    // accuracy anchor -- stays fp64.
    // -----------------------------------------------------------------
    double Bd[28];
#pragma unroll
    for (int z = 0; z < 28; ++z) Bd[z] = 0.0;

#pragma unroll
    for (int k = 0; k < 7; ++k) {
#pragma unroll
        for (int l = k + 1; l < 7; ++l) {
            double t[7];
#pragma unroll
            for (int j = 0; j < 7; ++j) t[j] = 0.0;

#pragma unroll
            for (int m = 0; m < 7; ++m) {
#pragma unroll
                for (int nn = m + 1; nn < 7; ++nn) {
                    if (m == k || m == l || nn == k || nn == l) continue;
                    int p = -1, q = -1, r = -1;
#pragma unroll
                    for (int x = 0; x < 7; ++x) {
                        if (x == k || x == l || x == m || x == nn) continue;
                        if (p < 0) p = x;
                        else if (q < 0) q = x;
                        else r = x;
                    }
                    const double es = eps_sign7(k, l, m, nn, p, q, r);
                    const double Cv = es * P[tri_idx(p, q, r)];   // exact (+-P)
#pragma unroll
                    for (int j = 0; j < 7; ++j) {
                        if (j == m || j == nn) continue;
                        int pi; double ps;
                        pf_ref(j, m, nn, pi, ps);
                        t[j] = fma(Cv * ps, P[pi], t[j]);         // exact product
                    }
                }
            }
#pragma unroll
            for (int i = 0; i < 7; ++i) {
                if (i == k || i == l) continue;
                int ai; double as;
                pf_ref(i, k, l, ai, as);
                const double av = as * P[ai];                      // exact
#pragma unroll
                for (int j = i; j < 7; ++j)
                    Bd[ui(i, j)] = fma(av, t[j], Bd[ui(i, j)]);
            }
        }
    }

    // Round the exact B to fp32. Symmetric eigenvalues are perfectly
    // conditioned: this perturbs them by <= eps32*||B||, ~1e-7 relative.
    float B[28];
#pragma unroll
    for (int z = 0; z < 28; ++z) B[z] = (float)(Bd[z] * (1.0 / 6.0));

    // -----------------------------------------------------------------
    // Cyclic Jacobi, all fp32: MUFU scalars, FFMA updates, packed
    // symmetric storage (Golub & Van Loan 8.4).
    // -----------------------------------------------------------------
#pragma unroll 1
    for (int sweep = 0; sweep < NSWEEP; ++sweep) {
#pragma unroll
        for (int p = 0; p < 7; ++p) {
#pragma unroll
            for (int q = p + 1; q < 7; ++q) {
                const float apq = B[ui(p, q)];
                const float app = B[ui(p, p)];
                const float aqq = B[ui(q, q)];

                const float theta = 0.5f * __fdividef(aqq - app, apq);
                // theta may be +-inf (apq tiny): sqf=inf -> tt=0 -> no-op.
                const float sqf = sqrtf(fmaf(theta, theta, 1.0f));
                float tt = __fdividef(1.0f, fabsf(theta) + sqf);
                tt = (theta < 0.0f) ? -tt : tt;
                tt = (apq == 0.0f) ? 0.0f : tt;   // kill 0/0 -> NaN case

                const float c = rsqrtf(fmaf(tt, tt, 1.0f));
                const float s = tt * c;

                // Diagonal + pivot updates.
                B[ui(p, p)] = fmaf(-tt, apq, app);
                B[ui(q, q)] = fmaf( tt, apq, aqq);
                B[ui(p, q)] = 0.0f;

                // Remaining rows/cols.
#pragma unroll
                for (int k2 = 0; k2 < 7; ++k2) {
                    if (k2 == p || k2 == q) continue;
                    const float akp = B[uis(k2, p)];
                    const float akq = B[uis(k2, q)];
                    B[uis(k2, p)] = fmaf(c, akp, -s * akq);
                    B[uis(k2, q)] = fmaf(s, akp,  c * akq);
                }
            }
        }
    }

    // det(Bm) = product of eigenvalues; s_den = (|det|+1e-12)^(1/9).
    float det = 1.0f;
#pragma unroll
    for (int i = 0; i < 7; ++i) det *= B[ui(i, i)];
    const float adet = fabsf(det) + 1e-12f;
    const float inv_s = exp2f(log2f(adet) * (-1.0f / 9.0f));

    // out = sum relu(EPS - lambda_i / s)
    float acc = 0.0f;
#pragma unroll
    for (int i = 0; i < 7; ++i)
        acc += fmaxf(0.0f, fmaf(-B[ui(i, i)], inv_s, 1e-6f));

    out[b] = acc;
}

// ---------------------------------------------------------------------------
extern "C" void kernel_launch(void* const* d_in, const int* in_sizes, int n_in,
                              void* d_out, int out_size)
{
    const float* phi = (const float*)d_in[0];
    float* out = (float*)d_out;
    const int n = in_sizes[0] / 35;   // batch count
    const int blocks = (n + TPB - 1) / TPB;
    positivity_kernel<<<blocks, TPB>>>(phi, out, n);
}

// round 7
// speedup vs baseline: 1.0003x; 1.0003x over previous
#include <cuda_runtime.h>

#define TPB 64
#define NSWEEP 6

// ---------------------------------------------------------------------------
// Compile-time index helpers (all call sites have constant args -> fold away).
// ---------------------------------------------------------------------------

// Lexicographic index of combination (a<b<c) out of C(7,3)=35.
__device__ __forceinline__ int tri_idx(int a, int b, int c) {
    int idx = 0;
#pragma unroll
    for (int x = 0; x < 7; ++x)
        if (x < a) idx += (6 - x) * (5 - x) / 2;
    idx += ((b - a - 1) * (12 - a - b)) / 2;
    idx += (c - b - 1);
    return idx;
}

// pf(a, m, n) with m<n, a distinct from both: phi index + sign.
__device__ __forceinline__ void pf_ref(int a, int m, int n, int &idx, double &sg) {
    if (a < m)      { idx = tri_idx(a, m, n); sg =  1.0; }
    else if (a < n) { idx = tri_idx(m, a, n); sg = -1.0; }
    else            { idx = tri_idx(m, n, a); sg =  1.0; }
}

// Sign of the permutation (k,l,m,n,p,q,r) of (0..6).
__device__ __forceinline__ double eps_sign7(int k, int l, int m, int n,
                                            int p, int q, int r) {
    int arr[7] = {k, l, m, n, p, q, r};
    int inv = 0;
#pragma unroll
    for (int x = 0; x < 7; ++x)
#pragma unroll
        for (int y = x + 1; y < 7; ++y)
            inv += (arr[x] > arr[y]) ? 1 : 0;
    return (inv & 1) ? -1.0 : 1.0;
}

// Upper-triangle packed index for 7x7 symmetric, requires i<=j.
__device__ __forceinline__ int ui(int i, int j) {
    return 7 * i - (i * (i - 1)) / 2 + (j - i);
}
__device__ __forceinline__ int uis(int i, int j) {   // symmetric access
    return (i <= j) ? ui(i, j) : ui(j, i);
}

// ---------------------------------------------------------------------------
// Kernel: one thread per batch element.
// ---------------------------------------------------------------------------
__global__ void __launch_bounds__(TPB)
positivity_kernel(const float* __restrict__ phi, float* __restrict__ out, int n)
{
    __shared__ float sphi[TPB * 35];

    const int base = blockIdx.x * TPB;
    {   // coalesced staging of this block's phi rows
        int limit = (n - base) * 35;
        if (limit > TPB * 35) limit = TPB * 35;
        for (int idx = threadIdx.x; idx < limit; idx += TPB)
            sphi[idx] = phi[(long long)base * 35 + idx];
    }
    __syncthreads();

    const int b = base + threadIdx.x;
    if (b >= n) return;

    // phi components, widened to double (exact).
    double P[35];
#pragma unroll
    for (int t = 0; t < 35; ++t) P[t] = (double)sphi[threadIdx.x * 35 + t];

    // -----------------------------------------------------------------
    // Bd[i<=j] (packed) = (1/6) * Sum_{k<l} pf(i,k,l) *
    //      Sum_{m<n in comp(k,l)} eps(k,l,m,n,p,q,r)*P[pqr]*pf(j,m,n)
    // Exact in fp64 (products of fp32-exact doubles are exact; the
    // cancellation-heavy additions carry 53 bits). This phase is the
    // accuracy anchor -- stays fp64.
    // -----------------------------------------------------------------
    double Bd[28];
#pragma unroll
    for (int z = 0; z < 28; ++z) Bd[z] = 0.0;

#pragma unroll
    for (int k = 0; k < 7; ++k) {
#pragma unroll
        for (int l = k + 1; l < 7; ++l) {
            double t[7];
#pragma unroll
            for (int j = 0; j < 7; ++j) t[j] = 0.0;

#pragma unroll
            for (int m = 0; m < 7; ++m) {
#pragma unroll
                for (int nn = m + 1; nn < 7; ++nn) {
                    if (m == k || m == l || nn == k || nn == l) continue;
                    int p = -1, q = -1, r = -1;
#pragma unroll
                    for (int x = 0; x < 7; ++x) {
                        if (x == k || x == l || x == m || x == nn) continue;
                        if (p < 0) p = x;
                        else if (q < 0) q = x;
                        else r = x;
                    }
                    const double es = eps_sign7(k, l, m, nn, p, q, r);
                    const double Cv = es * P[tri_idx(p, q, r)];   // exact (+-P)
#pragma unroll
                    for (int j = 0; j < 7; ++j) {
                        if (j == m || j == nn) continue;
                        int pi; double ps;
                        pf_ref(j, m, nn, pi, ps);
                        t[j] = fma(Cv * ps, P[pi], t[j]);         // exact product
                    }
                }
            }
#pragma unroll
            for (int i = 0; i < 7; ++i) {
                if (i == k || i == l) continue;
                int ai; double as;
                pf_ref(i, k, l, ai, as);
                const double av = as * P[ai];                      // exact
#pragma unroll
                for (int j = i; j < 7; ++j)
                    Bd[ui(i, j)] = fma(av, t[j], Bd[ui(i, j)]);
            }
        }
    }

    // Round the exact B to fp32. Symmetric eigenvalues are perfectly
    // conditioned: this perturbs them by <= eps32*||B||, ~1e-7 relative.
    float B[28];
#pragma unroll
    for (int z = 0; z < 28; ++z) B[z] = (float)(Bd[z] * (1.0 / 6.0));

    // -----------------------------------------------------------------
    // Cyclic Jacobi, all fp32: MUFU scalars, FFMA updates, packed
    // symmetric storage (Golub & Van Loan 8.4).
    // -----------------------------------------------------------------
#pragma unroll 1
    for (int sweep = 0; sweep < NSWEEP; ++sweep) {
#pragma unroll
        for (int p = 0; p < 7; ++p) {
#pragma unroll
            for (int q = p + 1; q < 7; ++q) {
                const float apq = B[ui(p, q)];
                const float app = B[ui(p, p)];
                const float aqq = B[ui(q, q)];

                const float theta = 0.5f * __fdividef(aqq - app, apq);
                // theta may be +-inf (apq tiny): sqf=inf -> tt=0 -> no-op.
                const float sqf = sqrtf(fmaf(theta, theta, 1.0f));
                float tt = __fdividef(1.0f, fabsf(theta) + sqf);
                tt = (theta < 0.0f) ? -tt : tt;
                tt = (apq == 0.0f) ? 0.0f : tt;   // kill 0/0 -> NaN case

                const float c = rsqrtf(fmaf(tt, tt, 1.0f));
                const float s = tt * c;

                // Diagonal + pivot updates.
                B[ui(p, p)] = fmaf(-tt, apq, app);
                B[ui(q, q)] = fmaf( tt, apq, aqq);
                B[ui(p, q)] = 0.0f;

                // Remaining rows/cols.
#pragma unroll
                for (int k2 = 0; k2 < 7; ++k2) {
                    if (k2 == p || k2 == q) continue;
                    const float akp = B[uis(k2, p)];
                    const float akq = B[uis(k2, q)];
                    B[uis(k2, p)] = fmaf(c, akp, -s * akq);
                    B[uis(k2, q)] = fmaf(s, akp,  c * akq);
                }
            }
        }
    }

    // det(Bm) = product of eigenvalues; s_den = (|det|+1e-12)^(1/9).
    float det = 1.0f;
#pragma unroll
    for (int i = 0; i < 7; ++i) det *= B[ui(i, i)];
    const float adet = fabsf(det) + 1e-12f;
    const float inv_s = exp2f(log2f(adet) * (-1.0f / 9.0f));

    // out = sum relu(EPS - lambda_i / s)
    float acc = 0.0f;
#pragma unroll
    for (int i = 0; i < 7; ++i)
        acc += fmaxf(0.0f, fmaf(-B[ui(i, i)], inv_s, 1e-6f));

    out[b] = acc;
}

// ---------------------------------------------------------------------------
extern "C" void kernel_launch(void* const* d_in, const int* in_sizes, int n_in,
                              void* d_out, int out_size)
{
    const float* phi = (const float*)d_in[0];
    float* out = (float*)d_out;
    const int n = in_sizes[0] / 35;   // batch count
    const int blocks = (n + TPB - 1) / TPB;
    positivity_kernel<<<blocks, TPB>>>(phi, out, n);
}

// round 8
// speedup vs baseline: 3.1719x; 3.1711x over previous
#include <cuda_runtime.h>

#define TPB 64
#define NSWEEP 6

// ---------------------------------------------------------------------------
// Compile-time index helpers (all call sites have constant args -> fold away).
// ---------------------------------------------------------------------------

// Lexicographic index of combination (a<b<c) out of C(7,3)=35.
__device__ __forceinline__ int tri_idx(int a, int b, int c) {
    int idx = 0;
#pragma unroll
    for (int x = 0; x < 7; ++x)
        if (x < a) idx += (6 - x) * (5 - x) / 2;
    idx += ((b - a - 1) * (12 - a - b)) / 2;
    idx += (c - b - 1);
    return idx;
}

// pf(a, m, n) with m<n, a distinct from both: phi index + sign (+-1).
__device__ __forceinline__ void pf_ref(int a, int m, int n, int &idx, float &sg) {
    if (a < m)      { idx = tri_idx(a, m, n); sg =  1.0f; }
    else if (a < n) { idx = tri_idx(m, a, n); sg = -1.0f; }
    else            { idx = tri_idx(m, n, a); sg =  1.0f; }
}

// Sign of the permutation (k,l,m,n,p,q,r) of (0..6).
__device__ __forceinline__ float eps_sign7(int k, int l, int m, int n,
                                           int p, int q, int r) {
    int arr[7] = {k, l, m, n, p, q, r};
    int inv = 0;
#pragma unroll
    for (int x = 0; x < 7; ++x)
#pragma unroll
        for (int y = x + 1; y < 7; ++y)
            inv += (arr[x] > arr[y]) ? 1 : 0;
    return (inv & 1) ? -1.0f : 1.0f;
}

// Upper-triangle packed index for 7x7 symmetric, requires i<=j.
__device__ __forceinline__ int ui(int i, int j) {
    return 7 * i - (i * (i - 1)) / 2 + (j - i);
}
__device__ __forceinline__ int uis(int i, int j) {   // symmetric access
    return (i <= j) ? ui(i, j) : ui(j, i);
}

// ---------------------------------------------------------------------------
// Kahan-compensated fp32 accumulator. True value = s - c.
// kacc adds a term given as (m, e1) where the true term is m + e1
// (e1 = exact FMA-captured rounding error of the product m).
// ---------------------------------------------------------------------------
struct KF { float s, c; };

__device__ __forceinline__ void kacc(KF &a, float m, float e1) {
    const float y  = m - a.c;
    const float t2 = a.s + y;
    a.c = ((t2 - a.s) - y) - e1;   // new rounding error minus pending term error
    a.s = t2;
}

// ---------------------------------------------------------------------------
// Kernel: one thread per batch element. All fp32; contraction compensated.
// ---------------------------------------------------------------------------
__global__ void __launch_bounds__(TPB)
positivity_kernel(const float* __restrict__ phi, float* __restrict__ out, int n)
{
    __shared__ float sphi[TPB * 35];

    const int base = blockIdx.x * TPB;
    {   // coalesced staging of this block's phi rows
        int limit = (n - base) * 35;
        if (limit > TPB * 35) limit = TPB * 35;
        for (int idx = threadIdx.x; idx < limit; idx += TPB)
            sphi[idx] = phi[(long long)base * 35 + idx];
    }
    __syncthreads();

    const int b = base + threadIdx.x;
    if (b >= n) return;

    float P[35];
#pragma unroll
    for (int t = 0; t < 35; ++t) P[t] = sphi[threadIdx.x * 35 + t];

    // -----------------------------------------------------------------
    // B[i<=j] (packed) = (1/6) * Sum_{k<l} pf(i,k,l) *
    //      Sum_{m<n in comp(k,l)} eps(k,l,m,n,p,q,r)*P[pqr]*pf(j,m,n)
    // Every product is (+-P[a])*P[b]; FMA error extraction + Kahan at
    // both accumulation levels reproduces the exact-fp64-then-round
    // result to ~eps^2. All full-rate FFMA, latency 4.
    // -----------------------------------------------------------------
    KF B[28];
#pragma unroll
    for (int z = 0; z < 28; ++z) { B[z].s = 0.0f; B[z].c = 0.0f; }

#pragma unroll
    for (int k = 0; k < 7; ++k) {
#pragma unroll
        for (int l = k + 1; l < 7; ++l) {
            KF t[7];
#pragma unroll
            for (int j = 0; j < 7; ++j) { t[j].s = 0.0f; t[j].c = 0.0f; }

#pragma unroll
            for (int m = 0; m < 7; ++m) {
#pragma unroll
                for (int nn = m + 1; nn < 7; ++nn) {
                    if (m == k || m == l || nn == k || nn == l) continue;
                    int p = -1, q = -1, r = -1;
#pragma unroll
                    for (int x = 0; x < 7; ++x) {
                        if (x == k || x == l || x == m || x == nn) continue;
                        if (p < 0) p = x;
                        else if (q < 0) q = x;
                        else r = x;
                    }
                    const float es = eps_sign7(k, l, m, nn, p, q, r);
                    const float Cv = es * P[tri_idx(p, q, r)];   // exact (+-P)
#pragma unroll
                    for (int j = 0; j < 7; ++j) {
                        if (j == m || j == nn) continue;
                        int pi; float ps;
                        pf_ref(j, m, nn, pi, ps);
                        const float x1 = (ps > 0.0f) ? Cv : -Cv; // free negate
                        const float mprod = x1 * P[pi];
                        const float eprod = fmaf(x1, P[pi], -mprod); // exact err
                        kacc(t[j], mprod, eprod);
                    }
                }
            }
#pragma unroll
            for (int i = 0; i < 7; ++i) {
                if (i == k || i == l) continue;
                int ai; float as;
                pf_ref(i, k, l, ai, as);
                const float av = (as > 0.0f) ? P[ai] : -P[ai];     // exact +-P
#pragma unroll
                for (int j = i; j < 7; ++j) {
                    // true term = av * (t.s - t.c)
                    const float mprod = av * t[j].s;
                    float e = fmaf(av, t[j].s, -mprod);            // product err
                    e = fmaf(av, -t[j].c, e);                      // fold -av*c
                    kacc(B[ui(i, j)], mprod, e);
                }
            }
        }
    }

    // Finalize: A = (B.s - B.c) / 6, fp32.
    float A[28];
#pragma unroll
    for (int z = 0; z < 28; ++z) A[z] = (B[z].s - B[z].c) * (1.0f / 6.0f);

    // -----------------------------------------------------------------
    // Cyclic Jacobi, all fp32, packed symmetric storage.
    // -----------------------------------------------------------------
#pragma unroll 1
    for (int sweep = 0; sweep < NSWEEP; ++sweep) {
#pragma unroll
        for (int p = 0; p < 7; ++p) {
#pragma unroll
            for (int q = p + 1; q < 7; ++q) {
                const float apq = A[ui(p, q)];
                const float app = A[ui(p, p)];
                const float aqq = A[ui(q, q)];

                float theta = 0.5f * __fdividef(aqq - app, apq);
                // Clamp so theta^2+1 stays finite (rsqrt(inf)*inf = NaN trap).
                theta = fminf(fmaxf(theta, -1e18f), 1e18f);
                const float x  = fmaf(theta, theta, 1.0f);
                const float sqf = x * rsqrtf(x);                 // sqrt(x)
                float tt = __fdividef(1.0f, fabsf(theta) + sqf);
                tt = (theta < 0.0f) ? -tt : tt;
                tt = (apq == 0.0f) ? 0.0f : tt;                  // 0/0 guard

                const float c  = rsqrtf(fmaf(tt, tt, 1.0f));
                const float s  = tt * c;
                const float ns = -s;

                // Diagonal + pivot updates.
                A[ui(p, p)] = fmaf(-tt, apq, app);
                A[ui(q, q)] = fmaf( tt, apq, aqq);
                A[ui(p, q)] = 0.0f;

                // Remaining rows/cols.
#pragma unroll
                for (int k2 = 0; k2 < 7; ++k2) {
                    if (k2 == p || k2 == q) continue;
                    const float akp = A[uis(k2, p)];
                    const float akq = A[uis(k2, q)];
                    A[uis(k2, p)] = fmaf(ns, akq, c * akp);
                    A[uis(k2, q)] = fmaf(s,  akp, c * akq);
                }
            }
        }
    }

    // det = product of eigenvalues; inv_s = (|det|+1e-12)^(-1/9).
    float det = 1.0f;
#pragma unroll
    for (int i = 0; i < 7; ++i) det *= A[ui(i, i)];
    const float adet  = fabsf(det) + 1e-12f;
    const float inv_s = exp2f(log2f(adet) * (-1.0f / 9.0f));

    // out = sum relu(EPS - lambda_i / s)
    float acc = 0.0f;
#pragma unroll
    for (int i = 0; i < 7; ++i)
        acc += fmaxf(0.0f, fmaf(-A[ui(i, i)], inv_s, 1e-6f));

    out[b] = acc;
}

// ---------------------------------------------------------------------------
extern "C" void kernel_launch(void* const* d_in, const int* in_sizes, int n_in,
                              void* d_out, int out_size)
{
    const float* phi = (const float*)d_in[0];
    float* out = (float*)d_out;
    const int n = in_sizes[0] / 35;   // batch count
    const int blocks = (n + TPB - 1) / TPB;
    positivity_kernel<<<blocks, TPB>>>(phi, out, n);
}